// round 5
// baseline (speedup 1.0000x reference)
#include <cuda_runtime.h>

#define BB   64
#define TT   512
#define HH   1024
#define CC   8
#define NROW 32768
#define LOGITS_OFF 1
#define PRED_OFF   (1 + 3*BB*TT*CC)
#define FULLM 0xFFFFFFFFu

// static device scratch
__device__ float g_expo[3 * NROW * CC];   // exp(logits)
__device__ float g_fwdP[192 * 8 * 64];    // forward chunk basis matrices
__device__ float g_vscr[192 * TT * CC];   // viterbi v_t

__device__ __forceinline__ void ffma2(unsigned long long& d,
                                      unsigned long long a,
                                      unsigned long long b) {
    asm("fma.rn.f32x2 %0, %1, %2, %0;" : "+l"(d) : "l"(a), "l"(b));
}
__device__ __forceinline__ void cpa16(unsigned sm, const void* g) {
    asm volatile("cp.async.cg.shared.global [%0], [%1], 16;" :: "r"(sm), "l"(g));
}

// ---------------------------------------------------------------------------
// GEMM: M=32768, N=24, K=1024.  256 blocks x 256 threads.
// Block tile 128 rows x 24 cols; thread = 4 rows x 3 cols. f32x2 FMA.
// Writes logits to out[1..] and exp(logits) to g_expo.
// ---------------------------------------------------------------------------
__global__ __launch_bounds__(256) void gemm_kernel(
    const float* __restrict__ enc, const float* __restrict__ W,
    const float* __restrict__ bias, float* __restrict__ out)
{
    __shared__ float As[2][128 * 20];
    __shared__ float Ws[2][24 * 20];

    const int tid  = threadIdx.x;
    const int rb   = blockIdx.x * 128;
    const int rgrp = tid & 31;          // row within tile (stride 32)
    const int c0   = (tid >> 5) * 3;    // 8 col-groups x 3 cols
    if (blockIdx.x == 0 && tid == 0) out[0] = 0.0f;

    unsigned long long acc[4][3];
    #pragma unroll
    for (int i = 0; i < 4; i++)
        #pragma unroll
        for (int m = 0; m < 3; m++) acc[i][m] = 0ull;

    unsigned asB[2] = { (unsigned)__cvta_generic_to_shared(&As[0][0]),
                        (unsigned)__cvta_generic_to_shared(&As[1][0]) };
    unsigned wsB[2] = { (unsigned)__cvta_generic_to_shared(&Ws[0][0]),
                        (unsigned)__cvta_generic_to_shared(&Ws[1][0]) };

    auto load_tiles = [&](int kb, int bf) {
        #pragma unroll
        for (int i = 0; i < 2; i++) {
            int idx = tid + i * 256;
            int row = idx >> 2, q = idx & 3;
            cpa16(asB[bf] + (row * 20 + q * 4) * 4,
                  enc + (size_t)(rb + row) * HH + kb + q * 4);
        }
        if (tid < 96) {
            int c = tid >> 2, q = tid & 3;
            cpa16(wsB[bf] + (c * 20 + q * 4) * 4, W + (size_t)c * HH + kb + q * 4);
        }
        asm volatile("cp.async.commit_group;");
    };

    load_tiles(0, 0);
    int buf = 0;
    for (int kb = 0; kb < HH; kb += 16, buf ^= 1) {
        if (kb + 16 < HH) {
            load_tiles(kb + 16, buf ^ 1);
            asm volatile("cp.async.wait_group 1;");
        } else {
            asm volatile("cp.async.wait_group 0;");
        }
        __syncthreads();
        #pragma unroll
        for (int k4 = 0; k4 < 16; k4 += 4) {
            ulonglong2 wv[3];
            #pragma unroll
            for (int m = 0; m < 3; m++)
                wv[m] = *reinterpret_cast<const ulonglong2*>(&Ws[buf][(c0 + m) * 20 + k4]);
            #pragma unroll
            for (int i = 0; i < 4; i++) {
                ulonglong2 av = *reinterpret_cast<const ulonglong2*>(
                    &As[buf][(rgrp + 32 * i) * 20 + k4]);
                #pragma unroll
                for (int m = 0; m < 3; m++) {
                    ffma2(acc[i][m], av.x, wv[m].x);
                    ffma2(acc[i][m], av.y, wv[m].y);
                }
            }
        }
        __syncthreads();
    }

    #pragma unroll
    for (int i = 0; i < 4; i++) {
        const int r = rb + rgrp + 32 * i;
        #pragma unroll
        for (int m = 0; m < 3; m++) {
            int col = c0 + m;
            int kt = col >> 3, cc = col & 7;
            float2 f = *reinterpret_cast<float2*>(&acc[i][m]);
            float val = f.x + f.y + bias[col];
            size_t base = ((size_t)kt * NROW + r) * 8 + cc;
            out[LOGITS_OFF + base] = val;
            g_expo[base] = __expf(val);
        }
    }
}

// ---------------------------------------------------------------------------
// scan: blocks 0..5   = exact Viterbi v-scan, 2 seqs per 8-lane group, stores v_t
//       blocks 6..101 = forward chunk basis matrices (linear domain)
// ---------------------------------------------------------------------------
__global__ __launch_bounds__(128) void scan_kernel(
    const float* __restrict__ start_t, const float* __restrict__ trans,
    const float* __restrict__ out)
{
    const int tid = threadIdx.x;

    if (blockIdx.x < 6) {
        const int j    = tid & 7;
        const int gidx = blockIdx.x * 16 + (tid >> 3);   // 0..95
        const int s0   = gidx * 2, s1 = gidx * 2 + 1;
        const int kt   = s0 >> 6;                        // same for s1
        const float* em0 = out + LOGITS_OFF + (size_t)s0 * (TT * CC);
        const float* em1 = out + LOGITS_OFF + (size_t)s1 * (TT * CC);
        float* vs0 = g_vscr + (size_t)s0 * (TT * CC);
        float* vs1 = g_vscr + (size_t)s1 * (TT * CC);

        float tr[8];
        #pragma unroll
        for (int i = 0; i < 8; i++) tr[i] = trans[kt * 64 + i * 8 + j];

        float v0 = start_t[kt * 8 + j] + em0[j];
        float v1 = start_t[kt * 8 + j] + em1[j];
        vs0[j] = v0; vs1[j] = v1;

        float eb0[8], eb1[8];
        #pragma unroll
        for (int u = 0; u < 8; u++) { eb0[u] = em0[(1 + u) * 8 + j]; eb1[u] = em1[(1 + u) * 8 + j]; }

        for (int tw = 1; tw < TT; tw += 8) {
            float nb0[8], nb1[8];
            #pragma unroll
            for (int u = 0; u < 8; u++) {
                int tn = tw + 8 + u;
                nb0[u] = (tn < TT) ? em0[tn * 8 + j] : 0.0f;
                nb1[u] = (tn < TT) ? em1[tn * 8 + j] : 0.0f;
            }
            #pragma unroll
            for (int u = 0; u < 8; u++) {
                int t = tw + u;
                if (t < TT) {
                    float a0 = __shfl_sync(FULLM, v0, 0, 8) + tr[0];
                    float b0 = __shfl_sync(FULLM, v1, 0, 8) + tr[0];
                    float a1 = __shfl_sync(FULLM, v0, 1, 8) + tr[1];
                    float b1 = __shfl_sync(FULLM, v1, 1, 8) + tr[1];
                    float a2 = __shfl_sync(FULLM, v0, 2, 8) + tr[2];
                    float b2 = __shfl_sync(FULLM, v1, 2, 8) + tr[2];
                    float a3 = __shfl_sync(FULLM, v0, 3, 8) + tr[3];
                    float b3 = __shfl_sync(FULLM, v1, 3, 8) + tr[3];
                    float a4 = __shfl_sync(FULLM, v0, 4, 8) + tr[4];
                    float b4 = __shfl_sync(FULLM, v1, 4, 8) + tr[4];
                    float a5 = __shfl_sync(FULLM, v0, 5, 8) + tr[5];
                    float b5 = __shfl_sync(FULLM, v1, 5, 8) + tr[5];
                    float a6 = __shfl_sync(FULLM, v0, 6, 8) + tr[6];
                    float b6 = __shfl_sync(FULLM, v1, 6, 8) + tr[6];
                    float a7 = __shfl_sync(FULLM, v0, 7, 8) + tr[7];
                    float b7 = __shfl_sync(FULLM, v1, 7, 8) + tr[7];
                    float m0 = fmaxf(fmaxf(fmaxf(a0, a1), fmaxf(a2, a3)),
                                     fmaxf(fmaxf(a4, a5), fmaxf(a6, a7)));
                    float m1 = fmaxf(fmaxf(fmaxf(b0, b1), fmaxf(b2, b3)),
                                     fmaxf(fmaxf(b4, b5), fmaxf(b6, b7)));
                    v0 = m0 + eb0[u];
                    v1 = m1 + eb1[u];
                    vs0[t * 8 + j] = v0;
                    vs1[t * 8 + j] = v1;
                }
            }
            #pragma unroll
            for (int u = 0; u < 8; u++) { eb0[u] = nb0[u]; eb1[u] = nb1[u]; }
        }
    } else {
        // forward chunks: thread = (seq s, chunk c, basis row ib)
        const int flat = (blockIdx.x - 6) * 128 + tid;
        const int ib = flat & 7;
        const int c  = (flat >> 3) & 7;
        const int s  = flat >> 6;
        const int kt = s >> 6;

        float ec[64];
        #pragma unroll
        for (int i = 0; i < 64; i++) ec[i] = __expf(trans[kt * 64 + i]) * 0.125f;

        float P[8];
        #pragma unroll
        for (int jj = 0; jj < 8; jj++) P[jj] = (jj == ib) ? 1.0f : 0.0f;

        const int tb = c * 64 + 1;
        const int te = (c * 64 + 64 < TT) ? c * 64 + 64 : TT - 1;
        const float* eo = g_expo + (size_t)s * (TT * CC);

        float4 pa0 = *reinterpret_cast<const float4*>(eo + tb * 8);
        float4 pb0 = *reinterpret_cast<const float4*>(eo + tb * 8 + 4);
        float4 pa1 = *reinterpret_cast<const float4*>(eo + (tb + 1) * 8);
        float4 pb1 = *reinterpret_cast<const float4*>(eo + (tb + 1) * 8 + 4);

        for (int t = tb; t <= te; t++) {
            float4 ca = pa0, cb = pb0;
            pa0 = pa1; pb0 = pb1;
            int tn = t + 2;
            if (tn <= te) {
                pa1 = *reinterpret_cast<const float4*>(eo + tn * 8);
                pb1 = *reinterpret_cast<const float4*>(eo + tn * 8 + 4);
            }
            float np[8];
            #pragma unroll
            for (int jj = 0; jj < 8; jj++) {
                float sum = P[0] * ec[jj];
                #pragma unroll
                for (int i = 1; i < 8; i++) sum = fmaf(P[i], ec[i * 8 + jj], sum);
                np[jj] = sum;
            }
            P[0] = np[0] * ca.x; P[1] = np[1] * ca.y;
            P[2] = np[2] * ca.z; P[3] = np[3] * ca.w;
            P[4] = np[4] * cb.x; P[5] = np[5] * cb.y;
            P[6] = np[6] * cb.z; P[7] = np[7] * cb.w;
        }
        float* dst = g_fwdP + ((size_t)(s * 8 + c) * 8 + ib) * 8;
        *reinterpret_cast<float4*>(dst)     = make_float4(P[0], P[1], P[2], P[3]);
        *reinterpret_cast<float4*>(dst + 4) = make_float4(P[4], P[5], P[6], P[7]);
    }
}

// ---------------------------------------------------------------------------
// final: blocks 0..95   = decode, 2 seqs/block, bp recomputed on-the-fly from v
//        blocks 96..107 = logZ combine + numerator + loss
// ---------------------------------------------------------------------------
__global__ __launch_bounds__(128) void final_kernel(
    const int* __restrict__ labels, const float* __restrict__ start_t,
    const float* __restrict__ end_t, const float* __restrict__ trans,
    float* __restrict__ out)
{
    const int tid = threadIdx.x;

    if (blockIdx.x < 96) {
        __shared__ unsigned char path[2][8][8][64];  // [seq][chunk][hyp][idx]
        __shared__ unsigned char sel[2][8];
        __shared__ float strT[64];                   // strT[tag*8+i] = trans[i*8+tag]

        const int local = tid >> 6;
        const int lt    = tid & 63;
        const int s     = blockIdx.x * 2 + local;    // both seqs share kt
        const int kt    = (blockIdx.x * 2) >> 6;

        if (tid < 64) strT[tid] = trans[kt * 64 + (tid & 7) * 8 + (tid >> 3)];
        __syncthreads();

        const float* vbase = g_vscr + (size_t)s * (TT * CC);

        {   // phase 1: walk each (chunk, exit hypothesis), recording tags
            const int c = lt >> 3, h = lt & 7;
            const int tb = c * 64 + 1;
            const int te = (c * 64 + 64 < TT) ? c * 64 + 64 : TT - 1;
            int tag = h;
            // prefetch v[t-1] two ahead (t descending)
            float4 pa0 = *reinterpret_cast<const float4*>(vbase + (te - 1) * 8);
            float4 pb0 = *reinterpret_cast<const float4*>(vbase + (te - 1) * 8 + 4);
            float4 pa1 = *reinterpret_cast<const float4*>(vbase + (te - 2) * 8);
            float4 pb1 = *reinterpret_cast<const float4*>(vbase + (te - 2) * 8 + 4);
            for (int t = te; t >= tb; t--) {
                float4 ca = pa0, cb = pb0;
                pa0 = pa1; pb0 = pb1;
                int tp = t - 3;
                if (tp >= tb - 1) {
                    pa1 = *reinterpret_cast<const float4*>(vbase + tp * 8);
                    pb1 = *reinterpret_cast<const float4*>(vbase + tp * 8 + 4);
                }
                const float* tc = &strT[tag * 8];
                float c0 = ca.x + tc[0], c1 = ca.y + tc[1];
                float c2 = ca.z + tc[2], c3 = ca.w + tc[3];
                float c4 = cb.x + tc[4], c5 = cb.y + tc[5];
                float c6 = cb.z + tc[6], c7 = cb.w + tc[7];
                float m = fmaxf(fmaxf(fmaxf(c0, c1), fmaxf(c2, c3)),
                                fmaxf(fmaxf(c4, c5), fmaxf(c6, c7)));
                unsigned mk = (c0 == m) ? 1u : 0u;
                mk |= (c1 == m) ? 2u : 0u;
                mk |= (c2 == m) ? 4u : 0u;
                mk |= (c3 == m) ? 8u : 0u;
                mk |= (c4 == m) ? 16u : 0u;
                mk |= (c5 == m) ? 32u : 0u;
                mk |= (c6 == m) ? 64u : 0u;
                mk |= (c7 == m) ? 128u : 0u;
                tag = __ffs(mk) - 1;
                path[local][c][h][t - tb] = (unsigned char)tag;
            }
        }
        __syncthreads();

        if (lt == 0) {  // phase 2: final argmax + compose chunk exits
            const float* v = vbase + (size_t)(TT - 1) * 8;
            float best = v[0] + end_t[kt * 8];
            int bi = 0;
            #pragma unroll
            for (int i = 1; i < 8; i++) {
                float cnd = v[i] + end_t[kt * 8 + i];
                if (cnd > best) { best = cnd; bi = i; }
            }
            int ex = bi;
            for (int cc = 7; cc >= 0; cc--) {
                sel[local][cc] = (unsigned char)ex;
                ex = path[local][cc][ex][0];
            }
        }
        __syncthreads();

        if (lt < 8) {   // phase 3: emit the selected path
            const int cc = lt;
            const int tb = cc * 64 + 1;
            const int te = (cc * 64 + 64 < TT) ? cc * 64 + 64 : TT - 1;
            const int stag = sel[local][cc];
            float* pred = out + PRED_OFF + (size_t)s * TT;
            pred[te] = (float)stag;
            const unsigned char* pp = &path[local][cc][stag][0];
            for (int idx = te - tb; idx >= 0; idx--)
                pred[tb - 1 + idx] = (float)pp[idx];
        }
    } else {
        const int g  = (blockIdx.x - 96) * 16 + (tid >> 3);   // seq 0..191
        const int j  = tid & 7;
        const int kt = g >> 6, b = g & 63;
        const float* em = out + LOGITS_OFF + (size_t)g * (TT * CC);
        const float LOG8 = 2.0794415416798357f;

        float a = start_t[kt * 8 + j] + em[j];
        for (int c = 0; c < 8; c++) {
            float n = (c < 7) ? 64.0f : 63.0f;
            const float* Pp = g_fwdP + (size_t)(g * 8 + c) * 64;
            float lm[8];
            #pragma unroll
            for (int i = 0; i < 8; i++)
                lm[i] = __logf(Pp[i * 8 + j]) + n * LOG8 + __shfl_sync(FULLM, a, i, 8);
            float m = fmaxf(fmaxf(fmaxf(lm[0], lm[1]), fmaxf(lm[2], lm[3])),
                            fmaxf(fmaxf(lm[4], lm[5]), fmaxf(lm[6], lm[7])));
            float ssum = 0.0f;
            #pragma unroll
            for (int i = 0; i < 8; i++) ssum += __expf(lm[i] - m);
            a = m + __logf(ssum);
        }
        float y = a + end_t[kt * 8 + j];
        float mm = y;
        #pragma unroll
        for (int d = 4; d > 0; d >>= 1) mm = fmaxf(mm, __shfl_xor_sync(FULLM, mm, d, 8));
        float q = __expf(y - mm);
        #pragma unroll
        for (int d = 4; d > 0; d >>= 1) q += __shfl_xor_sync(FULLM, q, d, 8);
        float logZ = mm + __logf(q);

        float num = 0.0f;
        for (int t = j; t < TT; t += 8) {
            int tg = labels[b * (3 * TT) + kt * TT + t];
            num += em[t * 8 + tg];
            if (t > 0) {
                int tp = labels[b * (3 * TT) + kt * TT + t - 1];
                num += trans[kt * 64 + tp * 8 + tg];
            } else {
                num += start_t[kt * 8 + tg];
            }
            if (t == TT - 1) num += end_t[kt * 8 + tg];
        }
        #pragma unroll
        for (int d = 4; d > 0; d >>= 1) num += __shfl_xor_sync(FULLM, num, d, 8);

        if (j == 0) atomicAdd(&out[0], logZ - num);
    }
}

extern "C" void kernel_launch(void* const* d_in, const int* in_sizes, int n_in,
                              void* d_out, int out_size)
{
    (void)in_sizes; (void)n_in; (void)out_size;
    const float* enc     = (const float*)d_in[0];
    const int*   labels  = (const int*)  d_in[1];
    const float* W       = (const float*)d_in[2];
    const float* bias    = (const float*)d_in[3];
    const float* start_t = (const float*)d_in[4];
    const float* end_t   = (const float*)d_in[5];
    const float* trans   = (const float*)d_in[6];
    float* out = (float*)d_out;

    gemm_kernel <<<256, 256>>>(enc, W, bias, out);
    scan_kernel <<<102, 128>>>(start_t, trans, out);
    final_kernel<<<108, 128>>>(labels, start_t, end_t, trans, out);
}

// round 8
// speedup vs baseline: 1.3140x; 1.3140x over previous
#include <cuda_runtime.h>

#define BB   64
#define TT   512
#define HH   1024
#define CC   8
#define NROW 32768
#define LOGITS_OFF 1
#define PRED_OFF   (1 + 3*BB*TT*CC)
#define FULLM 0xFFFFFFFFu

// static device scratch
__device__ float g_expo[3 * NROW * CC];   // exp(logits)

__device__ __forceinline__ void ffma2(unsigned long long& d,
                                      unsigned long long a,
                                      unsigned long long b) {
    asm("fma.rn.f32x2 %0, %1, %2, %0;" : "+l"(d) : "l"(a), "l"(b));
}
__device__ __forceinline__ void cpa16(unsigned sm, const void* g) {
    asm volatile("cp.async.cg.shared.global [%0], [%1], 16;" :: "r"(sm), "l"(g));
}

// ---------------------------------------------------------------------------
// GEMM: M=32768, N=24, K=1024.  256 blocks x 64 threads.
// Block tile 128 rows x 24 cols; thread = 8 rows x 6 cols (f32x2 FMA).
// Lane map: rgrp = tid>>2 (16 groups), cgrp = tid&3 (4 groups of 6 cols)
//   -> warp smem reads are 8-distinct-rows + broadcast: conflict-free.
// ---------------------------------------------------------------------------
__global__ __launch_bounds__(64) void gemm_kernel(
    const float* __restrict__ enc, const float* __restrict__ W,
    const float* __restrict__ bias, float* __restrict__ out)
{
    __shared__ float As[2][128 * 20];
    __shared__ float Ws[2][24 * 20];

    const int tid  = threadIdx.x;
    const int rb   = blockIdx.x * 128;
    const int rgrp = tid >> 2;          // 0..15, rows rgrp+16i
    const int c0   = (tid & 3) * 6;     // 6 cols
    if (blockIdx.x == 0 && tid == 0) out[0] = 0.0f;

    unsigned long long acc[8][6];
    #pragma unroll
    for (int i = 0; i < 8; i++)
        #pragma unroll
        for (int m = 0; m < 6; m++) acc[i][m] = 0ull;

    unsigned asB[2] = { (unsigned)__cvta_generic_to_shared(&As[0][0]),
                        (unsigned)__cvta_generic_to_shared(&As[1][0]) };
    unsigned wsB[2] = { (unsigned)__cvta_generic_to_shared(&Ws[0][0]),
                        (unsigned)__cvta_generic_to_shared(&Ws[1][0]) };

    auto load_tiles = [&](int kb, int bf) {
        #pragma unroll
        for (int i = 0; i < 8; i++) {
            int idx = tid + i * 64;
            int row = idx >> 2, q = idx & 3;
            cpa16(asB[bf] + (row * 20 + q * 4) * 4,
                  enc + (size_t)(rb + row) * HH + kb + q * 4);
        }
        #pragma unroll
        for (int i = 0; i < 2; i++) {
            int idx = tid + i * 64;
            if (idx < 96) {
                int c = idx >> 2, q = idx & 3;
                cpa16(wsB[bf] + (c * 20 + q * 4) * 4, W + (size_t)c * HH + kb + q * 4);
            }
        }
        asm volatile("cp.async.commit_group;");
    };

    load_tiles(0, 0);
    int buf = 0;
    for (int kb = 0; kb < HH; kb += 16, buf ^= 1) {
        if (kb + 16 < HH) {
            load_tiles(kb + 16, buf ^ 1);
            asm volatile("cp.async.wait_group 1;");
        } else {
            asm volatile("cp.async.wait_group 0;");
        }
        __syncthreads();
        #pragma unroll
        for (int k4 = 0; k4 < 16; k4 += 4) {
            ulonglong2 wv[6];
            #pragma unroll
            for (int m = 0; m < 6; m++)
                wv[m] = *reinterpret_cast<const ulonglong2*>(&Ws[buf][(c0 + m) * 20 + k4]);
            #pragma unroll
            for (int i = 0; i < 8; i++) {
                ulonglong2 av = *reinterpret_cast<const ulonglong2*>(
                    &As[buf][(rgrp + 16 * i) * 20 + k4]);
                #pragma unroll
                for (int m = 0; m < 6; m++) {
                    ffma2(acc[i][m], av.x, wv[m].x);
                    ffma2(acc[i][m], av.y, wv[m].y);
                }
            }
        }
        __syncthreads();
    }

    #pragma unroll
    for (int i = 0; i < 8; i++) {
        const int r = rb + rgrp + 16 * i;
        #pragma unroll
        for (int m = 0; m < 6; m++) {
            int col = c0 + m;
            int kt = col >> 3, cc = col & 7;
            float2 f = *reinterpret_cast<float2*>(&acc[i][m]);
            float val = f.x + f.y + bias[col];
            size_t base = ((size_t)kt * NROW + r) * 8 + cc;
            out[LOGITS_OFF + base] = val;
            g_expo[base] = __expf(val);
        }
    }
}

// ---------------------------------------------------------------------------
// crf2: 96 blocks x 192 threads, 2 sequences per block (same task kt).
// Phase A (parallel): warp0 lanes0-15 = viterbi chain (v -> smem);
//   warps1-4 = forward chunk basis matrices; warp5 lanes0-15 = numerator.
// Phase B: decode (128 thr, from smem v) + logZ combine/loss (warp0).
// ---------------------------------------------------------------------------
__global__ __launch_bounds__(192) void crf2_kernel(
    const int* __restrict__ labels, const float* __restrict__ start_t,
    const float* __restrict__ end_t, const float* __restrict__ trans,
    float* __restrict__ out)
{
    __shared__ float         vsm[2][TT][8];          // 32KB viterbi scores
    __shared__ float         Psm[2][8][8][8];        // [sl][chunk][ib][j]
    __shared__ unsigned char path[2][8][8][64];      // [sl][chunk][hyp][idx]
    __shared__ unsigned char sel[2][8];
    __shared__ float         strT[64];               // strT[tag*8+i] = trans[i*8+tag]
    __shared__ float         numsh[2];
    __shared__ int           lastsh[2];

    const int tid  = threadIdx.x;
    const int wid  = tid >> 5;
    const int lane = tid & 31;
    const int s0   = blockIdx.x * 2;
    const int kt   = s0 >> 6;

    if (tid < 64) strT[tid] = trans[kt * 64 + (tid & 7) * 8 + (tid >> 3)];

    if (wid == 0) {
        if (lane < 16) {
            // ---- Viterbi chain: lanes 0-7 = seq0 states, 8-15 = seq1 ----
            const int sl = lane >> 3, j = lane & 7;
            const int s  = s0 + sl;
            const float* em = out + LOGITS_OFF + (size_t)s * (TT * CC);

            float tr[8];
            #pragma unroll
            for (int i = 0; i < 8; i++) tr[i] = trans[kt * 64 + i * 8 + j];

            float v = start_t[kt * 8 + j] + em[j];
            vsm[sl][0][j] = v;

            float eb[8];
            #pragma unroll
            for (int u = 0; u < 8; u++) eb[u] = em[(1 + u) * 8 + j];

            for (int tw = 1; tw < TT; tw += 8) {
                float nb[8];
                #pragma unroll
                for (int u = 0; u < 8; u++) {
                    int tn = tw + 8 + u;
                    nb[u] = (tn < TT) ? em[tn * 8 + j] : 0.0f;
                }
                #pragma unroll
                for (int u = 0; u < 8; u++) {
                    int t = tw + u;
                    if (t < TT) {
                        float c0 = __shfl_sync(0xFFFFu, v, 0, 8) + tr[0];
                        float c1 = __shfl_sync(0xFFFFu, v, 1, 8) + tr[1];
                        float c2 = __shfl_sync(0xFFFFu, v, 2, 8) + tr[2];
                        float c3 = __shfl_sync(0xFFFFu, v, 3, 8) + tr[3];
                        float c4 = __shfl_sync(0xFFFFu, v, 4, 8) + tr[4];
                        float c5 = __shfl_sync(0xFFFFu, v, 5, 8) + tr[5];
                        float c6 = __shfl_sync(0xFFFFu, v, 6, 8) + tr[6];
                        float c7 = __shfl_sync(0xFFFFu, v, 7, 8) + tr[7];
                        float m = fmaxf(fmaxf(fmaxf(c0, c1), fmaxf(c2, c3)),
                                        fmaxf(fmaxf(c4, c5), fmaxf(c6, c7)));
                        v = m + eb[u];
                        vsm[sl][t][j] = v;
                    }
                }
                #pragma unroll
                for (int u = 0; u < 8; u++) eb[u] = nb[u];
            }

            // final argmax (strict >, first occurrence)
            float y = v + end_t[kt * 8 + j];
            float g[8];
            #pragma unroll
            for (int i = 0; i < 8; i++) g[i] = __shfl_sync(0xFFFFu, y, i, 8);
            float bv = g[0]; int last = 0;
            #pragma unroll
            for (int i = 1; i < 8; i++) { if (g[i] > bv) { bv = g[i]; last = i; } }
            if (j == 0) lastsh[sl] = last;
        }
    } else if (wid < 5) {
        // ---- forward chunk basis matrices (linear domain) ----
        const int idx = tid - 32;            // 0..127
        const int ib  = idx & 7;
        const int c   = (idx >> 3) & 7;
        const int sl  = idx >> 6;
        const int s   = s0 + sl;

        float ec[64];
        #pragma unroll
        for (int i = 0; i < 64; i++) ec[i] = __expf(trans[kt * 64 + i]) * 0.125f;

        float P[8];
        #pragma unroll
        for (int jj = 0; jj < 8; jj++) P[jj] = (jj == ib) ? 1.0f : 0.0f;

        const int tb = c * 64 + 1;
        const int te = (c * 64 + 64 < TT) ? c * 64 + 64 : TT - 1;
        const float* eo = g_expo + (size_t)s * (TT * CC);

        float4 pa0 = *reinterpret_cast<const float4*>(eo + tb * 8);
        float4 pb0 = *reinterpret_cast<const float4*>(eo + tb * 8 + 4);
        float4 pa1 = *reinterpret_cast<const float4*>(eo + (tb + 1) * 8);
        float4 pb1 = *reinterpret_cast<const float4*>(eo + (tb + 1) * 8 + 4);

        for (int t = tb; t <= te; t++) {
            float4 ca = pa0, cb = pb0;
            pa0 = pa1; pb0 = pb1;
            int tn = t + 2;
            if (tn <= te) {
                pa1 = *reinterpret_cast<const float4*>(eo + tn * 8);
                pb1 = *reinterpret_cast<const float4*>(eo + tn * 8 + 4);
            }
            float np[8];
            #pragma unroll
            for (int jj = 0; jj < 8; jj++) {
                float sum = P[0] * ec[jj];
                #pragma unroll
                for (int i = 1; i < 8; i++) sum = fmaf(P[i], ec[i * 8 + jj], sum);
                np[jj] = sum;
            }
            P[0] = np[0] * ca.x; P[1] = np[1] * ca.y;
            P[2] = np[2] * ca.z; P[3] = np[3] * ca.w;
            P[4] = np[4] * cb.x; P[5] = np[5] * cb.y;
            P[6] = np[6] * cb.z; P[7] = np[7] * cb.w;
        }
        #pragma unroll
        for (int jj = 0; jj < 8; jj++) Psm[sl][c][ib][jj] = P[jj];
    } else {
        // ---- numerator (gold path score) ----
        if (lane < 16) {
            const int sl = lane >> 3, j = lane & 7;
            const int s  = s0 + sl, b = s & 63;
            const float* em = out + LOGITS_OFF + (size_t)s * (TT * CC);
            float num = 0.0f;
            for (int t = j; t < TT; t += 8) {
                int tg = labels[b * (3 * TT) + kt * TT + t];
                num += em[t * 8 + tg];
                if (t > 0) {
                    int tp = labels[b * (3 * TT) + kt * TT + t - 1];
                    num += trans[kt * 64 + tp * 8 + tg];
                } else {
                    num += start_t[kt * 8 + tg];
                }
                if (t == TT - 1) num += end_t[kt * 8 + tg];
            }
            #pragma unroll
            for (int d = 4; d > 0; d >>= 1) num += __shfl_xor_sync(0xFFFFu, num, d, 8);
            if (j == 0) numsh[sl] = num;
        }
    }
    __syncthreads();

    if (tid >= 64) {
        // ---- decode phase 1: per (seq, chunk, hypothesis) backtrace ----
        const int did   = tid - 64;
        const int local = did >> 6;
        const int lt    = did & 63;
        const int c  = lt >> 3, h = lt & 7;
        const int tb = c * 64 + 1;
        const int te = (c * 64 + 64 < TT) ? c * 64 + 64 : TT - 1;
        int tag = h;
        for (int t = te; t >= tb; t--) {
            float4 va = *reinterpret_cast<const float4*>(&vsm[local][t - 1][0]);
            float4 vb = *reinterpret_cast<const float4*>(&vsm[local][t - 1][4]);
            const float* tc = &strT[tag * 8];
            float c0 = va.x + tc[0], c1 = va.y + tc[1];
            float c2 = va.z + tc[2], c3 = va.w + tc[3];
            float c4 = vb.x + tc[4], c5 = vb.y + tc[5];
            float c6 = vb.z + tc[6], c7 = vb.w + tc[7];
            float m = fmaxf(fmaxf(fmaxf(c0, c1), fmaxf(c2, c3)),
                            fmaxf(fmaxf(c4, c5), fmaxf(c6, c7)));
            unsigned mk = (c0 == m) ? 1u : 0u;
            mk |= (c1 == m) ? 2u : 0u;
            mk |= (c2 == m) ? 4u : 0u;
            mk |= (c3 == m) ? 8u : 0u;
            mk |= (c4 == m) ? 16u : 0u;
            mk |= (c5 == m) ? 32u : 0u;
            mk |= (c6 == m) ? 64u : 0u;
            mk |= (c7 == m) ? 128u : 0u;
            tag = __ffs(mk) - 1;
            path[local][c][h][t - tb] = (unsigned char)tag;
        }
    } else if (tid < 32 && lane < 16) {
        // ---- logZ combine + loss ----
        const int sl = lane >> 3, j = lane & 7;
        const int s  = s0 + sl;
        const float* em = out + LOGITS_OFF + (size_t)s * (TT * CC);
        const float LOG8 = 2.0794415416798357f;

        float a = start_t[kt * 8 + j] + em[j];
        for (int c = 0; c < 8; c++) {
            float n = (c < 7) ? 64.0f : 63.0f;
            float lm[8];
            #pragma unroll
            for (int i = 0; i < 8; i++)
                lm[i] = __logf(Psm[sl][c][i][j]) + n * LOG8 + __shfl_sync(0xFFFFu, a, i, 8);
            float m = fmaxf(fmaxf(fmaxf(lm[0], lm[1]), fmaxf(lm[2], lm[3])),
                            fmaxf(fmaxf(lm[4], lm[5]), fmaxf(lm[6], lm[7])));
            float ssum = 0.0f;
            #pragma unroll
            for (int i = 0; i < 8; i++) ssum += __expf(lm[i] - m);
            a = m + __logf(ssum);
        }
        float y = a + end_t[kt * 8 + j];
        float mm = y;
        #pragma unroll
        for (int d = 4; d > 0; d >>= 1) mm = fmaxf(mm, __shfl_xor_sync(0xFFFFu, mm, d, 8));
        float q = __expf(y - mm);
        #pragma unroll
        for (int d = 4; d > 0; d >>= 1) q += __shfl_xor_sync(0xFFFFu, q, d, 8);
        float logZ = mm + __logf(q);
        if (j == 0) atomicAdd(&out[0], logZ - numsh[sl]);
    }
    __syncthreads();

    if (tid == 64 || tid == 128) {
        const int local = (tid - 64) >> 6;
        int ex = lastsh[local];
        for (int cc = 7; cc >= 0; cc--) {
            sel[local][cc] = (unsigned char)ex;
            ex = path[local][cc][ex][0];
        }
    }
    __syncthreads();

    if (tid >= 64) {
        const int did   = tid - 64;
        const int local = did >> 6;
        const int lt    = did & 63;
        if (lt < 8) {
            const int cc = lt;
            const int tb = cc * 64 + 1;
            const int te = (cc * 64 + 64 < TT) ? cc * 64 + 64 : TT - 1;
            const int stag = sel[local][cc];
            float* pred = out + PRED_OFF + (size_t)(s0 + local) * TT;
            pred[te] = (float)stag;
            const unsigned char* pp = &path[local][cc][stag][0];
            for (int idx = te - tb; idx >= 0; idx--)
                pred[tb - 1 + idx] = (float)pp[idx];
        }
    }
}

extern "C" void kernel_launch(void* const* d_in, const int* in_sizes, int n_in,
                              void* d_out, int out_size)
{
    (void)in_sizes; (void)n_in; (void)out_size;
    const float* enc     = (const float*)d_in[0];
    const int*   labels  = (const int*)  d_in[1];
    const float* W       = (const float*)d_in[2];
    const float* bias    = (const float*)d_in[3];
    const float* start_t = (const float*)d_in[4];
    const float* end_t   = (const float*)d_in[5];
    const float* trans   = (const float*)d_in[6];
    float* out = (float*)d_out;

    gemm_kernel<<<256, 64>>>(enc, W, bias, out);
    crf2_kernel<<<96, 192>>>(labels, start_t, end_t, trans, out);
}